// round 2
// baseline (speedup 1.0000x reference)
#include <cuda_runtime.h>
#include <math.h>

#define BB 64
#define NN 8732
#define CC 21
#define MM 16
#define BN (BB*NN)

// ---- scratch (no allocations allowed) ----
__device__ float        g_vbuf[BN];          // -log_softmax_bg per anchor (0 if assigned)
__device__ int          g_ktab[BB*MM];
__device__ int          g_ctab[BB*MM];
__device__ unsigned int g_hist1[4096];
__device__ unsigned int g_h2c[4096];
__device__ float        g_h2s[4096];
__device__ double       g_posCe;
__device__ double       g_negHi;
__device__ double       g_bboxSum;
__device__ int          g_posCnt;
__device__ int          g_validCnt;
__device__ int          g_b0;
__device__ int          g_cntAbove1;

__device__ __forceinline__ float smooth_l1(float d) {
    float a = fabsf(d);
    return a < 1.0f ? 0.5f * d * d : a - 0.5f;
}

// K0: zero scratch
__global__ void k_init() {
    int i = blockIdx.x * blockDim.x + threadIdx.x;
    if (i < 4096) {
        g_hist1[i] = 0u;
        g_h2c[i]   = 0u;
        g_h2s[i]   = 0.0f;
    }
    if (i == 0) {
        g_posCe = 0.0; g_negHi = 0.0; g_bboxSum = 0.0;
        g_posCnt = 0;  g_validCnt = 0; g_b0 = 0; g_cntAbove1 = 0;
    }
}

// K1: parse targets, build (k,cls) tables, full bbox loss numerator + counts
__global__ void k_parse(const float* __restrict__ target,
                        const float* __restrict__ predBoxes,
                        const float* __restrict__ bboxOut) {
    int b = blockIdx.x;
    int m = threadIdx.x;                 // 16 threads
    const float* t = target + b * (1 + 6 * MM);
    int num = (int)t[0];
    const float* e = t + 1 + 6 * m;
    int   ci = (int)e[0];
    int   k  = (int)e[5];
    bool valid = (m < num);

    g_ktab[b * MM + m] = valid ? k : -1;
    g_ctab[b * MM + m] = (valid && ci > 0) ? ci : 0;

    if (valid) {
        atomicAdd(&g_validCnt, 1);
        if (ci > 0) atomicAdd(&g_posCnt, 1);

        float tx1 = e[1], ty1 = e[2], tx2 = e[3], ty2 = e[4];
        const float* p = predBoxes + (size_t)k * 4;
        float px1 = p[0], py1 = p[1], px2 = p[2], py2 = p[3];
        float pw = px2 - px1, ph = py2 - py1;
        float eb0 = ((tx1 + tx2) * 0.5f - (px1 + px2) * 0.5f) / pw;
        float eb1 = ((ty1 + ty2) * 0.5f - (py1 + py2) * 0.5f) / ph;
        float eb2 = logf((tx2 - tx1) / pw);
        float eb3 = logf((ty2 - ty1) / ph);

        const float* bo = bboxOut + ((size_t)b * NN + (size_t)k) * 4;
        float s = smooth_l1(bo[0] - eb0) + smooth_l1(bo[1] - eb1)
                + smooth_l1(bo[2] - eb2) + smooth_l1(bo[3] - eb3);
        atomicAdd(&g_bboxSum, (double)s);
    }
}

// K2: per-anchor log-softmax; positive CE; v-buffer + level-1 histogram
__global__ void __launch_bounds__(256) k_main(const float* __restrict__ conf) {
    __shared__ int sk[MM], sc[MM];
    __shared__ unsigned int sh[4096];
    int tid = threadIdx.x;
    int b = blockIdx.y;
    if (tid < MM) { sk[tid] = g_ktab[b * MM + tid]; sc[tid] = g_ctab[b * MM + tid]; }
    for (int i = tid; i < 4096; i += blockDim.x) sh[i] = 0u;
    __syncthreads();

    int n = blockIdx.x * blockDim.x + tid;
    if (n < NN) {
        const float* row = conf + ((size_t)b * NN + (size_t)n) * CC;
        float r[CC];
#pragma unroll
        for (int c = 0; c < CC; c++) r[c] = __ldg(row + c);
        float mx = r[0];
#pragma unroll
        for (int c = 1; c < CC; c++) mx = fmaxf(mx, r[c]);
        float se = 0.0f;
#pragma unroll
        for (int c = 0; c < CC; c++) se += __expf(r[c] - mx);
        float logZ = mx + __logf(se);

        int cls = -1;  // -1 = unassigned
#pragma unroll
        for (int m = 0; m < MM; m++)
            if (sk[m] == n) cls = sc[m];

        size_t idx = (size_t)b * NN + (size_t)n;
        if (cls < 0) {
            float v = fmaxf(logZ - r[0], 0.0f);   // -log_softmax of background, >= 0
            g_vbuf[idx] = v;
            atomicAdd(&sh[__float_as_uint(v) >> 20], 1u);
        } else {
            g_vbuf[idx] = 0.0f;                   // assigned: excluded from negatives
            if (cls > 0) {
                float x = __ldg(row + cls);
                atomicAdd(&g_posCe, (double)(logZ - x));
            }
        }
    }
    __syncthreads();
    for (int i = tid; i < 4096; i += blockDim.x) {
        unsigned int c = sh[i];
        if (c) atomicAdd(&g_hist1[i], c);
    }
}

// K3: find level-1 boundary bin
__global__ void k_scan1() {
    if (threadIdx.x == 0) {
        int K = 3 * g_posCnt;
        int acc = 0, b0 = 0;
        for (int b = 4095; b >= 0; b--) {
            int h = (int)g_hist1[b];
            if (acc + h >= K) { b0 = b; break; }
            acc += h;
        }
        g_b0 = b0;
        g_cntAbove1 = acc;
    }
}

// K4: exact sum above boundary bin; level-2 histogram of boundary bin
__global__ void __launch_bounds__(256) k_pass2() {
    int i = blockIdx.x * blockDim.x + threadIdx.x;
    if (i >= BN) return;
    int b0 = g_b0;
    float v = g_vbuf[i];
    unsigned int bits = __float_as_uint(v);
    if (bits == 0u) return;
    int t12 = (int)(bits >> 20);
    if (t12 > b0) {
        atomicAdd(&g_negHi, (double)v);
    } else if (t12 == b0) {
        unsigned int b2 = (bits >> 8) & 0xFFFu;
        atomicAdd(&g_h2c[b2], 1u);
        atomicAdd(&g_h2s[b2], v);
    }
}

// K5: finalize losses
__global__ void k_final(float* __restrict__ out) {
    if (threadIdx.x == 0) {
        int K = 3 * g_posCnt;
        int r = K - g_cntAbove1;
        if (r < 0) r = 0;
        double s = g_negHi;
        for (int b = 4095; b >= 0 && r > 0; b--) {
            int c = (int)g_h2c[b];
            if (!c) continue;
            float bs = g_h2s[b];
            if (c <= r) { s += (double)bs; r -= c; }
            else        { s += (double)bs * (double)r / (double)c; r = 0; }
        }
        long long selCnt = (long long)g_posCnt + (long long)K;
        if (selCnt < 1) selCnt = 1;
        double conf_loss = (g_posCe + s) / (double)selCnt;
        long long denomB = 4LL * (long long)g_validCnt;
        if (denomB < 1) denomB = 1;
        double bbox_loss = g_bboxSum / (double)denomB;
        out[0] = (float)conf_loss;
        out[1] = (float)bbox_loss;
    }
}

extern "C" void kernel_launch(void* const* d_in, const int* in_sizes, int n_in,
                              void* d_out, int out_size) {
    const float* conf   = (const float*)d_in[0];   // (B, N, C)
    const float* bbox   = (const float*)d_in[1];   // (B, N, 4)
    const float* target = (const float*)d_in[2];   // (B, 1+6M)
    const float* pred   = (const float*)d_in[3];   // (N, 4)
    float* out = (float*)d_out;

    k_init<<<16, 256>>>();
    k_parse<<<BB, MM>>>(target, pred, bbox);
    dim3 g((NN + 255) / 256, BB);
    k_main<<<g, 256>>>(conf);
    k_scan1<<<1, 32>>>();
    k_pass2<<<(BN + 255) / 256, 256>>>();
    k_final<<<1, 32>>>(out);
}

// round 3
// speedup vs baseline: 10.4083x; 10.4083x over previous
#include <cuda_runtime.h>
#include <math.h>

#define BB 64
#define NN 8732
#define CC 21
#define MM 16
#define BN (BB*NN)

// ---- scratch (no allocations allowed) ----
__device__ float        g_vbuf[BN];          // -log_softmax_bg per anchor (0 if assigned)
__device__ int          g_ktab[BB*MM];
__device__ int          g_ctab[BB*MM];
__device__ unsigned int g_hist1[4096];
__device__ unsigned int g_h2c[4096];
__device__ float        g_h2s[4096];
__device__ double       g_posCe;
__device__ double       g_negHi;
__device__ double       g_bboxSum;
__device__ int          g_posCnt;
__device__ int          g_validCnt;
__device__ int          g_b0;
__device__ int          g_cntAbove1;

__device__ __forceinline__ float smooth_l1(float d) {
    float a = fabsf(d);
    return a < 1.0f ? 0.5f * d * d : a - 0.5f;
}

// K0: zero scratch
__global__ void k_init() {
    int i = blockIdx.x * blockDim.x + threadIdx.x;
    if (i < 4096) {
        g_hist1[i] = 0u;
        g_h2c[i]   = 0u;
        g_h2s[i]   = 0.0f;
    }
    if (i == 0) {
        g_posCe = 0.0; g_negHi = 0.0; g_bboxSum = 0.0;
        g_posCnt = 0;  g_validCnt = 0; g_b0 = 0; g_cntAbove1 = 0;
    }
}

// K1: parse targets, build (k,cls) tables, full bbox loss numerator + counts
__global__ void k_parse(const float* __restrict__ target,
                        const float* __restrict__ predBoxes,
                        const float* __restrict__ bboxOut) {
    int b = blockIdx.x;
    int m = threadIdx.x;                 // 16 threads
    const float* t = target + b * (1 + 6 * MM);
    int num = (int)t[0];
    const float* e = t + 1 + 6 * m;
    int   ci = (int)e[0];
    int   k  = (int)e[5];
    bool valid = (m < num);

    g_ktab[b * MM + m] = valid ? k : -1;
    g_ctab[b * MM + m] = (valid && ci > 0) ? ci : 0;

    if (valid) {
        atomicAdd(&g_validCnt, 1);
        if (ci > 0) atomicAdd(&g_posCnt, 1);

        float tx1 = e[1], ty1 = e[2], tx2 = e[3], ty2 = e[4];
        const float* p = predBoxes + (size_t)k * 4;
        float px1 = p[0], py1 = p[1], px2 = p[2], py2 = p[3];
        float pw = px2 - px1, ph = py2 - py1;
        float eb0 = ((tx1 + tx2) * 0.5f - (px1 + px2) * 0.5f) / pw;
        float eb1 = ((ty1 + ty2) * 0.5f - (py1 + py2) * 0.5f) / ph;
        float eb2 = logf((tx2 - tx1) / pw);
        float eb3 = logf((ty2 - ty1) / ph);

        const float* bo = bboxOut + ((size_t)b * NN + (size_t)k) * 4;
        float s = smooth_l1(bo[0] - eb0) + smooth_l1(bo[1] - eb1)
                + smooth_l1(bo[2] - eb2) + smooth_l1(bo[3] - eb3);
        atomicAdd(&g_bboxSum, (double)s);
    }
}

// K2: per-anchor log-softmax; positive CE; v-buffer + level-1 histogram
__global__ void __launch_bounds__(256) k_main(const float* __restrict__ conf) {
    __shared__ int sk[MM], sc[MM];
    __shared__ unsigned int sh[4096];
    int tid = threadIdx.x;
    int b = blockIdx.y;
    if (tid < MM) { sk[tid] = g_ktab[b * MM + tid]; sc[tid] = g_ctab[b * MM + tid]; }
    for (int i = tid; i < 4096; i += blockDim.x) sh[i] = 0u;
    __syncthreads();

    int n = blockIdx.x * blockDim.x + tid;
    if (n < NN) {
        const float* row = conf + ((size_t)b * NN + (size_t)n) * CC;
        float r[CC];
#pragma unroll
        for (int c = 0; c < CC; c++) r[c] = __ldg(row + c);
        float mx = r[0];
#pragma unroll
        for (int c = 1; c < CC; c++) mx = fmaxf(mx, r[c]);
        float se = 0.0f;
#pragma unroll
        for (int c = 0; c < CC; c++) se += __expf(r[c] - mx);
        float logZ = mx + __logf(se);

        int cls = -1;  // -1 = unassigned
#pragma unroll
        for (int m = 0; m < MM; m++)
            if (sk[m] == n) cls = sc[m];

        size_t idx = (size_t)b * NN + (size_t)n;
        if (cls < 0) {
            float v = fmaxf(logZ - r[0], 0.0f);   // -log_softmax of background, >= 0
            g_vbuf[idx] = v;
            atomicAdd(&sh[__float_as_uint(v) >> 20], 1u);
        } else {
            g_vbuf[idx] = 0.0f;                   // assigned: excluded from negatives
            if (cls > 0) {
                float x = __ldg(row + cls);
                atomicAdd(&g_posCe, (double)(logZ - x));
            }
        }
    }
    __syncthreads();
    for (int i = tid; i < 4096; i += blockDim.x) {
        unsigned int c = sh[i];
        if (c) atomicAdd(&g_hist1[i], c);
    }
}

// K3: find level-1 boundary bin — parallel suffix scan (1 block, 1024 threads)
__global__ void __launch_bounds__(1024) k_scan1() {
    __shared__ unsigned int sh[4096];
    __shared__ unsigned int ssum[1024];
    int tid = threadIdx.x;

    // load histogram (4 bins per thread, coalesced)
#pragma unroll
    for (int j = 0; j < 4; j++)
        sh[tid + j * 1024] = g_hist1[tid + j * 1024];
    __syncthreads();

    // chunk t covers bins [4t, 4t+4)
    unsigned int c0 = sh[4 * tid], c1 = sh[4 * tid + 1],
                 c2 = sh[4 * tid + 2], c3 = sh[4 * tid + 3];
    ssum[tid] = c0 + c1 + c2 + c3;
    __syncthreads();

    // inclusive suffix sum over chunk sums: ssum[t] = sum_{j>=t} chunk[j]
    for (int off = 1; off < 1024; off <<= 1) {
        unsigned int v = (tid + off < 1024) ? ssum[tid + off] : 0u;
        __syncthreads();
        ssum[tid] += v;
        __syncthreads();
    }

    int K = 3 * g_posCnt;
    unsigned int chunkExcl = (tid < 1023) ? ssum[tid + 1] : 0u;  // suffix excl of chunk

    // per-bin suffix_excl within chunk (descending)
    unsigned int e3 = chunkExcl;
    unsigned int e2 = e3 + c3;
    unsigned int e1 = e2 + c2;
    unsigned int e0 = e1 + c1;
    unsigned int ex[4] = {e0, e1, e2, e3};
    unsigned int cn[4] = {c0, c1, c2, c3};
#pragma unroll
    for (int j = 0; j < 4; j++) {
        if ((int)ex[j] < K && (int)(ex[j] + cn[j]) >= K) {
            g_b0 = 4 * tid + j;
            g_cntAbove1 = (int)ex[j];
        }
    }
    if (tid == 0 && (int)ssum[0] < K) {   // degenerate: fewer candidates than K
        g_b0 = 0;
        g_cntAbove1 = (int)ssum[0];
    }
}

// K4: exact sum above boundary bin; level-2 histogram of boundary bin
__global__ void __launch_bounds__(256) k_pass2() {
    int i = blockIdx.x * blockDim.x + threadIdx.x;
    if (i >= BN) return;
    int b0 = g_b0;
    float v = g_vbuf[i];
    unsigned int bits = __float_as_uint(v);
    if (bits == 0u) return;
    int t12 = (int)(bits >> 20);
    if (t12 > b0) {
        atomicAdd(&g_negHi, (double)v);
    } else if (t12 == b0) {
        unsigned int b2 = (bits >> 8) & 0xFFFu;
        atomicAdd(&g_h2c[b2], 1u);
        atomicAdd(&g_h2s[b2], v);
    }
}

// K5: finalize — parallel suffix scan over level-2 histogram + reduction
__global__ void __launch_bounds__(1024) k_final(float* __restrict__ out) {
    __shared__ unsigned int shc[4096];
    __shared__ float        shs[4096];
    __shared__ unsigned int ssum[1024];
    __shared__ double       sred[1024];
    int tid = threadIdx.x;

#pragma unroll
    for (int j = 0; j < 4; j++) {
        shc[tid + j * 1024] = g_h2c[tid + j * 1024];
        shs[tid + j * 1024] = g_h2s[tid + j * 1024];
    }
    __syncthreads();

    unsigned int c0 = shc[4 * tid], c1 = shc[4 * tid + 1],
                 c2 = shc[4 * tid + 2], c3 = shc[4 * tid + 3];
    ssum[tid] = c0 + c1 + c2 + c3;
    __syncthreads();
    for (int off = 1; off < 1024; off <<= 1) {
        unsigned int v = (tid + off < 1024) ? ssum[tid + off] : 0u;
        __syncthreads();
        ssum[tid] += v;
        __syncthreads();
    }

    int K = 3 * g_posCnt;
    long long r = (long long)K - (long long)g_cntAbove1;
    if (r < 0) r = 0;

    unsigned int chunkExcl = (tid < 1023) ? ssum[tid + 1] : 0u;
    unsigned int e3 = chunkExcl;
    unsigned int e2 = e3 + c3;
    unsigned int e1 = e2 + c2;
    unsigned int e0 = e1 + c1;
    unsigned int ex[4] = {e0, e1, e2, e3};
    unsigned int cn[4] = {c0, c1, c2, c3};

    double local = 0.0;
#pragma unroll
    for (int j = 0; j < 4; j++) {
        unsigned int c = cn[j];
        if (c) {
            long long rem = r - (long long)ex[j];      // remaining budget at this bin
            long long take = rem < 0 ? 0 : (rem > (long long)c ? (long long)c : rem);
            if (take > 0) {
                float bs = shs[4 * tid + j];
                local += (double)bs * ((double)take / (double)c);  // take==c -> exact bs
            }
        }
    }
    sred[tid] = local;
    __syncthreads();
    for (int off = 512; off > 0; off >>= 1) {
        if (tid < off) sred[tid] += sred[tid + off];
        __syncthreads();
    }

    if (tid == 0) {
        double s = g_negHi + sred[0];
        long long selCnt = (long long)g_posCnt + (long long)K;
        if (selCnt < 1) selCnt = 1;
        double conf_loss = (g_posCe + s) / (double)selCnt;
        long long denomB = 4LL * (long long)g_validCnt;
        if (denomB < 1) denomB = 1;
        double bbox_loss = g_bboxSum / (double)denomB;
        out[0] = (float)conf_loss;
        out[1] = (float)bbox_loss;
    }
}

extern "C" void kernel_launch(void* const* d_in, const int* in_sizes, int n_in,
                              void* d_out, int out_size) {
    const float* conf   = (const float*)d_in[0];   // (B, N, C)
    const float* bbox   = (const float*)d_in[1];   // (B, N, 4)
    const float* target = (const float*)d_in[2];   // (B, 1+6M)
    const float* pred   = (const float*)d_in[3];   // (N, 4)
    float* out = (float*)d_out;

    k_init<<<16, 256>>>();
    k_parse<<<BB, MM>>>(target, pred, bbox);
    dim3 g((NN + 255) / 256, BB);
    k_main<<<g, 256>>>(conf);
    k_scan1<<<1, 1024>>>();
    k_pass2<<<(BN + 255) / 256, 256>>>();
    k_final<<<1, 1024>>>(out);
}